// round 13
// baseline (speedup 1.0000x reference)
#include <cuda_runtime.h>
#include <cuda_fp16.h>
#include <math.h>
#include <stdint.h>

#define BATCH 4
#define SEQ   2048
#define DM    768
#define NH    12
#define HD    64
#define MROWS (BATCH*SEQ)   // 8192
#define BHT   (BATCH*NH)    // 48

// ---------------- misc helpers ----------------
__device__ __forceinline__ uint32_t s2u(const void* p) {
    uint32_t a;
    asm("{ .reg .u64 t; cvta.to.shared.u64 t, %1; cvt.u32.u64 %0, t; }"
        : "=r"(a) : "l"(p));
    return a;
}
// cp.async 16B (sm_80 PTX)
__device__ __forceinline__ void cpa16(uint32_t dst, const void* src) {
    asm volatile("cp.async.cg.shared.global [%0], [%1], 16;"
                 :: "r"(dst), "l"(src) : "memory");
}
#define CP_COMMIT() asm volatile("cp.async.commit_group;" ::: "memory")
#define CP_WAIT0()  asm volatile("cp.async.wait_group 0;" ::: "memory")

// ---------------- mma.sync helpers (sm_80 PTX, legacy HMMA) ----------------
__device__ __forceinline__ void ldsm_x4(uint32_t* r, uint32_t addr) {
    asm volatile("ldmatrix.sync.aligned.m8n8.x4.shared.b16 {%0,%1,%2,%3}, [%4];"
                 : "=r"(r[0]), "=r"(r[1]), "=r"(r[2]), "=r"(r[3]) : "r"(addr));
}
__device__ __forceinline__ void ldsm_x4t(uint32_t* r, uint32_t addr) {
    asm volatile("ldmatrix.sync.aligned.m8n8.x4.trans.shared.b16 {%0,%1,%2,%3}, [%4];"
                 : "=r"(r[0]), "=r"(r[1]), "=r"(r[2]), "=r"(r[3]) : "r"(addr));
}
// fp16 mma
__device__ __forceinline__ void mma_f16(float* c, const uint32_t* a, const uint32_t* b) {
    asm volatile(
        "mma.sync.aligned.m16n8k16.row.col.f32.f16.f16.f32 "
        "{%0,%1,%2,%3}, {%4,%5,%6,%7}, {%8,%9}, {%0,%1,%2,%3};"
        : "+f"(c[0]), "+f"(c[1]), "+f"(c[2]), "+f"(c[3])
        : "r"(a[0]), "r"(a[1]), "r"(a[2]), "r"(a[3]), "r"(b[0]), "r"(b[1]));
}
// fp16 pack (low half = a)
__device__ __forceinline__ uint32_t packf16(float a, float b) {
    __half2 h = __floats2half2_rn(a, b);
    return *reinterpret_cast<uint32_t*>(&h);
}
// fp16 split: hi pair + residual pair
__device__ __forceinline__ void splitf16(float a, float b, uint32_t& h, uint32_t& l) {
    __half2 hh = __floats2half2_rn(a, b);
    float2 bk = __half22float2(hh);
    __half2 ll = __floats2half2_rn(a - bk.x, b - bk.y);
    h = *reinterpret_cast<uint32_t*>(&hh);
    l = *reinterpret_cast<uint32_t*>(&ll);
}
// STS single fp16 pairs
__device__ __forceinline__ void stsA(float4 v, uint32_t* base, int idx) {
    *reinterpret_cast<uint2*>(base + idx) =
        make_uint2(packf16(v.x, v.y), packf16(v.z, v.w));
}
// STS fp16 hi + residual lo
__device__ __forceinline__ void stsB(float4 v, uint32_t* bH, uint32_t* bL, int idx) {
    uint32_t h0, l0, h1, l1;
    splitf16(v.x, v.y, h0, l0);
    splitf16(v.z, v.w, h1, l1);
    *reinterpret_cast<uint2*>(bH + idx) = make_uint2(h0, h1);
    *reinterpret_cast<uint2*>(bL + idx) = make_uint2(l0, l1);
}

// Scratch. Q/K/V single fp16 pairs. Q PRE-SCALED by 1/8 (exact, power of 2).
__device__ uint32_t g_Qf[(size_t)BHT*SEQ*HD/2];
__device__ uint32_t g_Kf[(size_t)BHT*SEQ*HD/2];
__device__ uint32_t g_Vf[(size_t)BHT*SEQ*HD/2];
__device__ float    g_OH[(size_t)MROWS*DM];      // attention out f32, [b,s,h*64+d]

// ---------------------------------------------------------------------------
// fp16 mma.sync GEMM: C[8192x768] = A @ W.
// modes 0-2 (QKV): 1-term (A, W both single fp16).
// mode 3 (Wo):     2-term (W = Wh + Wl residual) -> lin_out f32.
// 128x128 CTA tile, BK=32, 8 warps (2M x 4N), double-buffered smem.
// ---------------------------------------------------------------------------
__global__ __launch_bounds__(256, 2) void mma_gemm(
    const float* __restrict__ Ain,
    const float* __restrict__ W0, const float* __restrict__ W1,
    const float* __restrict__ W2,
    float* __restrict__ lin_out, int base_mode)
{
    extern __shared__ uint32_t smg[];
    // per-buffer (u32): A 0 (128x20), Bh 2560 (32x68), Bl 4736; stride 6912
    const uint32_t BUFU = 6912;

    int mode = base_mode + blockIdx.z;
    bool bt = (mode == 3);   // 2-term only for Wo
    const float* W = (mode == 0) ? W0 : (mode == 1) ? W1 : (mode == 2) ? W2 : W0;
    const float* A = (mode == 3) ? (const float*)g_OH : Ain;

    int tid  = threadIdx.x;
    int wid  = tid >> 5, lane = tid & 31;
    int warpM = wid & 1, warpN = wid >> 1;
    int m0 = blockIdx.y * 128, n0 = blockIdx.x * 128;

    float acc[4][4][4];
    #pragma unroll
    for (int i = 0; i < 4; i++)
        #pragma unroll
        for (int j = 0; j < 4; j++)
            #pragma unroll
            for (int k = 0; k < 4; k++) acc[i][j][k] = 0.f;

    uint32_t sbg = s2u(smg);
    uint32_t aLane = (uint32_t)((lane & 15) * 80 + (lane >> 4) * 16 + warpM * 5120);
    uint32_t bLane = (uint32_t)((lane & 15) * 272 + (lane >> 4) * 16 + warpN * 64);

    float4 av[4], bv[4];
    // LDG chunk 0, STS buf0
    #pragma unroll
    for (int it = 0; it < 4; it++) {
        int i = tid + it * 256;
        int r = i >> 3, c4 = (i & 7) * 4;
        av[it] = *reinterpret_cast<const float4*>(A + (size_t)(m0 + r) * DM + c4);
        int rb = i >> 5, cb = (i & 31) * 4;
        bv[it] = *reinterpret_cast<const float4*>(W + (size_t)rb * DM + n0 + cb);
    }
    #pragma unroll
    for (int it = 0; it < 4; it++) {
        int i = tid + it * 256;
        int r = i >> 3, c4 = (i & 7) * 4;
        stsA(av[it], smg, r * 20 + (c4 >> 1));
        int rb = i >> 5, cb = (i & 31) * 4;
        if (bt) stsB(bv[it], smg + 2560, smg + 4736, rb * 68 + (cb >> 1));
        else    stsA(bv[it], smg + 2560, rb * 68 + (cb >> 1));
    }
    // LDG chunk 1 into regs
    #pragma unroll
    for (int it = 0; it < 4; it++) {
        int i = tid + it * 256;
        int r = i >> 3, c4 = (i & 7) * 4;
        av[it] = *reinterpret_cast<const float4*>(A + (size_t)(m0 + r) * DM + 32 + c4);
        int rb = i >> 5, cb = (i & 31) * 4;
        bv[it] = *reinterpret_cast<const float4*>(W + (size_t)(32 + rb) * DM + n0 + cb);
    }
    __syncthreads();

    for (int c = 0; c < 24; c++) {
        if (c < 23) {
            uint32_t* base = smg + ((c + 1) & 1) * BUFU;
            #pragma unroll
            for (int it = 0; it < 4; it++) {
                int i = tid + it * 256;
                int r = i >> 3, c4 = (i & 7) * 4;
                stsA(av[it], base, r * 20 + (c4 >> 1));
                int rb = i >> 5, cb = (i & 31) * 4;
                if (bt) stsB(bv[it], base + 2560, base + 4736, rb * 68 + (cb >> 1));
                else    stsA(bv[it], base + 2560, rb * 68 + (cb >> 1));
            }
        }
        if (c < 22) {
            int k0n = (c + 2) * 32;
            #pragma unroll
            for (int it = 0; it < 4; it++) {
                int i = tid + it * 256;
                int r = i >> 3, c4 = (i & 7) * 4;
                av[it] = *reinterpret_cast<const float4*>(
                    A + (size_t)(m0 + r) * DM + k0n + c4);
                int rb = i >> 5, cb = (i & 31) * 4;
                bv[it] = *reinterpret_cast<const float4*>(
                    W + (size_t)(k0n + rb) * DM + n0 + cb);
            }
        }
        uint32_t off = sbg + (uint32_t)(c & 1) * (BUFU * 4);
        uint32_t aH = off, bH = off + 10240, bL = off + 18944;
        #pragma unroll
        for (int ks = 0; ks < 2; ks++) {
            uint32_t bh[4][2], bl[4][2];
            #pragma unroll
            for (int np = 0; np < 2; np++) {
                uint32_t r4[4];
                ldsm_x4t(r4, bH + bLane + ks * 4352 + np * 32);
                bh[np*2][0] = r4[0]; bh[np*2][1] = r4[1];
                bh[np*2+1][0] = r4[2]; bh[np*2+1][1] = r4[3];
                if (bt) {
                    ldsm_x4t(r4, bL + bLane + ks * 4352 + np * 32);
                    bl[np*2][0] = r4[0]; bl[np*2][1] = r4[1];
                    bl[np*2+1][0] = r4[2]; bl[np*2+1][1] = r4[3];
                }
            }
            #pragma unroll
            for (int mtp = 0; mtp < 2; mtp++) {
                uint32_t a0h[4], a1h[4];
                ldsm_x4(a0h, aH + aLane + (2*mtp) * 1280 + ks * 32);
                ldsm_x4(a1h, aH + aLane + (2*mtp+1) * 1280 + ks * 32);
                #pragma unroll
                for (int nt = 0; nt < 4; nt++) mma_f16(acc[2*mtp][nt],   a0h, bh[nt]);
                #pragma unroll
                for (int nt = 0; nt < 4; nt++) mma_f16(acc[2*mtp+1][nt], a1h, bh[nt]);
                if (bt) {
                    #pragma unroll
                    for (int nt = 0; nt < 4; nt++) mma_f16(acc[2*mtp][nt],   a0h, bl[nt]);
                    #pragma unroll
                    for (int nt = 0; nt < 4; nt++) mma_f16(acc[2*mtp+1][nt], a1h, bl[nt]);
                }
            }
        }
        __syncthreads();
    }

    int rl = lane >> 2, cl = (lane & 3) * 2;
    if (mode == 3) {
        #pragma unroll
        for (int mt = 0; mt < 4; mt++) {
            int m = m0 + warpM * 64 + mt * 16 + rl;
            #pragma unroll
            for (int nt = 0; nt < 4; nt++) {
                int n = n0 + warpN * 32 + nt * 8 + cl;
                *reinterpret_cast<float2*>(lin_out + (size_t)m * DM + n) =
                    make_float2(acc[mt][nt][0], acc[mt][nt][1]);
                *reinterpret_cast<float2*>(lin_out + (size_t)(m + 8) * DM + n) =
                    make_float2(acc[mt][nt][2], acc[mt][nt][3]);
            }
        }
    } else {
        // Q pre-scaled by 1/8 (exact power-of-2)
        float alpha = (mode == 0) ? 0.125f : 1.0f;
        uint32_t* dst = (mode == 0) ? g_Qf : (mode == 1) ? g_Kf : g_Vf;
        #pragma unroll
        for (int mt = 0; mt < 4; mt++) {
            int m = m0 + warpM * 64 + mt * 16 + rl;
            int b = m >> 11, s = m & 2047;
            #pragma unroll
            for (int nt = 0; nt < 4; nt++) {
                int n = n0 + warpN * 32 + nt * 8 + cl;
                int h = n >> 6, d = n & 63;
                size_t base = ((size_t)(b * NH + h) * SEQ + s) * 32 + (d >> 1);
                dst[base] = packf16(acc[mt][nt][0] * alpha, acc[mt][nt][1] * alpha);
                dst[base + 8 * 32] = packf16(acc[mt][nt][2] * alpha, acc[mt][nt][3] * alpha);
            }
        }
    }
}

// ---------------------------------------------------------------------------
// Flash attention, no-max-tracking softmax (logits bounded ~|6|, exp safe):
// S = Qf.Kf^T fp16 single-term (Q pre-scaled), P = exp(S_masked) directly,
// O += P.V (single fp16). Double-buffered K/V/kmask, one sync + one wait/tile.
// ---------------------------------------------------------------------------
__global__ __launch_bounds__(256, 2) void flash_mma(
    const float* __restrict__ q_mask, float* __restrict__ logits)
{
    extern __shared__ uint32_t sm32[];
    uint32_t sb = s2u(sm32);
    const uint32_t oQ = 0;
    const uint32_t oK[2]  = {18432u, 27648u};
    const uint32_t oV[2]  = {36864u, 46080u};
    const uint32_t oKM[2] = {55296u, 55552u};

    int bh = blockIdx.y;
    int b  = bh / NH;
    int h  = bh - b * NH;
    int q0 = blockIdx.x * 128;
    int tid = threadIdx.x;
    int w = tid >> 5, lane = tid & 31;
    int rq = lane >> 2, cq = lane & 3;

    #pragma unroll
    for (int it = 0; it < 4; it++) {
        int i = tid + it * 256;
        int r = i >> 3, ch = i & 7;
        size_t src = ((size_t)(bh * SEQ + q0 + r)) * 32 + ch * 4;
        cpa16(sb + oQ + r * 144 + ch * 16, g_Qf + src);
    }
    #pragma unroll
    for (int it = 0; it < 2; it++) {
        int i = tid + it * 256;
        int r = i >> 3, ch = i & 7;
        size_t src = ((size_t)(bh * SEQ + r)) * 32 + ch * 4;
        cpa16(sb + oK[0] + r * 144 + ch * 16, g_Kf + src);
        cpa16(sb + oV[0] + r * 144 + ch * 16, g_Vf + src);
    }
    if (tid < 16)
        cpa16(sb + oKM[0] + tid * 16, q_mask + (size_t)b * SEQ + tid * 4);
    CP_COMMIT();

    int rowA = 16 * w + rq;
    float qmA = q_mask[(size_t)b * SEQ + q0 + rowA];
    float qmB = q_mask[(size_t)b * SEQ + q0 + rowA + 8];
    float sA = 0.f, sB = 0.f;
    float o[8][4];
    #pragma unroll
    for (int i = 0; i < 8; i++)
        #pragma unroll
        for (int j = 0; j < 4; j++) o[i][j] = 0.f;
    uint32_t qh[4][4];

    float* LA = logits + ((size_t)bh * SEQ + q0 + rowA) * SEQ + 2 * cq;
    float* LB = LA + (size_t)8 * SEQ;

    for (int t = 0; t < 32; t++) {
        int k0 = t * 64;
        int bi = t & 1;
        CP_WAIT0();
        __syncthreads();

        if (t == 0) {
            uint32_t qoff = (uint32_t)((16 * w + (lane & 15)) * 144 + (lane >> 4) * 16);
            #pragma unroll
            for (int ks = 0; ks < 4; ks++)
                ldsm_x4(qh[ks], sb + oQ + qoff + ks * 32);
        }
        if (t + 1 < 32) {
            int nb = (t + 1) & 1;
            int k1 = k0 + 64;
            #pragma unroll
            for (int it = 0; it < 2; it++) {
                int i = tid + it * 256;
                int r = i >> 3, ch = i & 7;
                size_t src = ((size_t)(bh * SEQ + k1 + r)) * 32 + ch * 4;
                cpa16(sb + oK[nb] + r * 144 + ch * 16, g_Kf + src);
                cpa16(sb + oV[nb] + r * 144 + ch * 16, g_Vf + src);
            }
            if (tid < 16)
                cpa16(sb + oKM[nb] + tid * 16, q_mask + (size_t)b * SEQ + k1 + tid * 4);
            CP_COMMIT();
        }

        // ---- S = Q.K^T (Q pre-scaled: S is final raw logits) ----
        uint32_t kb = sb + oK[bi];
        float s[8][4];
        #pragma unroll
        for (int i = 0; i < 8; i++)
            #pragma unroll
            for (int j = 0; j < 4; j++) s[i][j] = 0.f;
        #pragma unroll
        for (int ks = 0; ks < 4; ks++) {
            uint32_t kf[4][4];
            #pragma unroll
            for (int g = 0; g < 4; g++) {
                uint32_t koff = (uint32_t)((16 * g + (lane & 15)) * 144
                                           + (lane >> 4) * 16 + ks * 32);
                ldsm_x4(kf[g], kb + koff);
            }
            #pragma unroll
            for (int g = 0; g < 4; g++) { uint32_t b2[2] = {kf[g][0], kf[g][2]}; mma_f16(s[2*g],   qh[ks], b2); }
            #pragma unroll
            for (int g = 0; g < 4; g++) { uint32_t b2[2] = {kf[g][1], kf[g][3]}; mma_f16(s[2*g+1], qh[ks], b2); }
        }

        // raw logits out
        #pragma unroll
        for (int j = 0; j < 8; j++) {
            *reinterpret_cast<float2*>(LA + k0 + 8 * j) = make_float2(s[j][0], s[j][1]);
            *reinterpret_cast<float2*>(LB + k0 + 8 * j) = make_float2(s[j][2], s[j][3]);
        }

        // ---- mask + direct exp (no max tracking; logits bounded) ----
        const float* smKM = reinterpret_cast<const float*>(
            reinterpret_cast<const char*>(sm32) + oKM[bi]);
        #pragma unroll
        for (int j = 0; j < 8; j++) {
            float km0 = smKM[8 * j + 2 * cq], km1 = smKM[8 * j + 2 * cq + 1];
            float uA0 = 1.0f - qmA * km0, uA1 = 1.0f - qmA * km1;
            float uB0 = 1.0f - qmB * km0, uB1 = 1.0f - qmB * km1;
            s[j][0] = __expf(fmaf(-1e5f, uA0, s[j][0]));
            s[j][1] = __expf(fmaf(-1e5f, uA1, s[j][1]));
            s[j][2] = __expf(fmaf(-1e5f, uB0, s[j][2]));
            s[j][3] = __expf(fmaf(-1e5f, uB1, s[j][3]));
            sA += s[j][0] + s[j][1];
            sB += s[j][2] + s[j][3];
        }

        // ---- O += P.V ----
        uint32_t vb = sb + oV[bi];
        #pragma unroll
        for (int ks = 0; ks < 4; ks++) {
            uint32_t pa[4];
            pa[0] = packf16(s[2*ks][0],   s[2*ks][1]);
            pa[1] = packf16(s[2*ks][2],   s[2*ks][3]);
            pa[2] = packf16(s[2*ks+1][0], s[2*ks+1][1]);
            pa[3] = packf16(s[2*ks+1][2], s[2*ks+1][3]);
            uint32_t vf[4][4];
            #pragma unroll
            for (int dg = 0; dg < 4; dg++) {
                uint32_t voff = (uint32_t)((16 * ks + (lane & 15)) * 144
                                           + (lane >> 4) * 16 + dg * 32);
                ldsm_x4t(vf[dg], vb + voff);
            }
            #pragma unroll
            for (int dg = 0; dg < 4; dg++) { uint32_t b2[2] = {vf[dg][0], vf[dg][1]}; mma_f16(o[2*dg],   pa, b2); }
            #pragma unroll
            for (int dg = 0; dg < 4; dg++) { uint32_t b2[2] = {vf[dg][2], vf[dg][3]}; mma_f16(o[2*dg+1], pa, b2); }
        }
    }

    // final sum reduce + normalize + store
    sA += __shfl_xor_sync(0xffffffffu, sA, 1);
    sA += __shfl_xor_sync(0xffffffffu, sA, 2);
    sB += __shfl_xor_sync(0xffffffffu, sB, 1);
    sB += __shfl_xor_sync(0xffffffffu, sB, 2);
    float invA = 1.0f / sA, invB = 1.0f / sB;
    float* OA = g_OH + ((size_t)b * SEQ + q0 + rowA) * DM + h * HD + 2 * cq;
    float* OB = OA + (size_t)8 * DM;
    #pragma unroll
    for (int dt = 0; dt < 8; dt++) {
        *reinterpret_cast<float2*>(OA + 8 * dt) =
            make_float2(o[dt][0] * invA, o[dt][1] * invA);
        *reinterpret_cast<float2*>(OB + 8 * dt) =
            make_float2(o[dt][2] * invB, o[dt][3] * invB);
    }
}

// ---------------------------------------------------------------------------
// Launch. Output: [out (4*2048*768)] then [logits_raw (48*2048*2048)]
// ---------------------------------------------------------------------------
extern "C" void kernel_launch(void* const* d_in, const int* in_sizes, int n_in,
                              void* d_out, int out_size)
{
    const float* x  = (const float*)d_in[0];
    const float* qm = (const float*)d_in[1];
    const float* Wq = (const float*)d_in[2];
    const float* Wk = (const float*)d_in[3];
    const float* Wv = (const float*)d_in[4];
    const float* Wo = (const float*)d_in[5];

    float* out    = (float*)d_out;
    float* logits = out + (size_t)MROWS * DM;

    const int GEMM_SMEM  = 55296;   // 2 x 6912 u32
    const int FLASH_SMEM = 55808;
    cudaFuncSetAttribute(mma_gemm,
                         cudaFuncAttributeMaxDynamicSharedMemorySize, GEMM_SMEM);
    cudaFuncSetAttribute(flash_mma,
                         cudaFuncAttributeMaxDynamicSharedMemorySize, FLASH_SMEM);

    mma_gemm <<<dim3(6, 64, 3), 256, GEMM_SMEM>>>(x, Wq, Wk, Wv, nullptr, 0);
    flash_mma<<<dim3(16, 48), 256, FLASH_SMEM>>>(qm, logits);
    mma_gemm <<<dim3(6, 64, 1), 256, GEMM_SMEM>>>(nullptr, Wo, Wo, Wo, out, 3);
}

// round 14
// speedup vs baseline: 1.3056x; 1.3056x over previous
#include <cuda_runtime.h>
#include <cuda_fp16.h>
#include <math.h>
#include <stdint.h>

#define BATCH 4
#define SEQ   2048
#define DM    768
#define NH    12
#define HD    64
#define MROWS (BATCH*SEQ)   // 8192
#define BHT   (BATCH*NH)    // 48

// ---------------- misc helpers ----------------
__device__ __forceinline__ uint32_t s2u(const void* p) {
    uint32_t a;
    asm("{ .reg .u64 t; cvta.to.shared.u64 t, %1; cvt.u32.u64 %0, t; }"
        : "=r"(a) : "l"(p));
    return a;
}
// cp.async 16B (sm_80 PTX)
__device__ __forceinline__ void cpa16(uint32_t dst, const void* src) {
    asm volatile("cp.async.cg.shared.global [%0], [%1], 16;"
                 :: "r"(dst), "l"(src) : "memory");
}
#define CP_COMMIT() asm volatile("cp.async.commit_group;" ::: "memory")
#define CP_WAIT0()  asm volatile("cp.async.wait_group 0;" ::: "memory")
// streaming store (evict-first): logits written once, never read
__device__ __forceinline__ void stg_cs_f2(float* p, float a, float b) {
    asm volatile("st.global.cs.v2.f32 [%0], {%1,%2};"
                 :: "l"(p), "f"(a), "f"(b) : "memory");
}

// ---------------- mma.sync helpers (sm_80 PTX, legacy HMMA) ----------------
__device__ __forceinline__ void ldsm_x4(uint32_t* r, uint32_t addr) {
    asm volatile("ldmatrix.sync.aligned.m8n8.x4.shared.b16 {%0,%1,%2,%3}, [%4];"
                 : "=r"(r[0]), "=r"(r[1]), "=r"(r[2]), "=r"(r[3]) : "r"(addr));
}
__device__ __forceinline__ void ldsm_x4t(uint32_t* r, uint32_t addr) {
    asm volatile("ldmatrix.sync.aligned.m8n8.x4.trans.shared.b16 {%0,%1,%2,%3}, [%4];"
                 : "=r"(r[0]), "=r"(r[1]), "=r"(r[2]), "=r"(r[3]) : "r"(addr));
}
// fp16 mma
__device__ __forceinline__ void mma_f16(float* c, const uint32_t* a, const uint32_t* b) {
    asm volatile(
        "mma.sync.aligned.m16n8k16.row.col.f32.f16.f16.f32 "
        "{%0,%1,%2,%3}, {%4,%5,%6,%7}, {%8,%9}, {%0,%1,%2,%3};"
        : "+f"(c[0]), "+f"(c[1]), "+f"(c[2]), "+f"(c[3])
        : "r"(a[0]), "r"(a[1]), "r"(a[2]), "r"(a[3]), "r"(b[0]), "r"(b[1]));
}
// fp16 pack (low half = a)
__device__ __forceinline__ uint32_t packf16(float a, float b) {
    __half2 h = __floats2half2_rn(a, b);
    return *reinterpret_cast<uint32_t*>(&h);
}
// fp16 split: hi pair + residual pair
__device__ __forceinline__ void splitf16(float a, float b, uint32_t& h, uint32_t& l) {
    __half2 hh = __floats2half2_rn(a, b);
    float2 bk = __half22float2(hh);
    __half2 ll = __floats2half2_rn(a - bk.x, b - bk.y);
    h = *reinterpret_cast<uint32_t*>(&hh);
    l = *reinterpret_cast<uint32_t*>(&ll);
}
// STS A: single fp16 (no residual)
__device__ __forceinline__ void stsA(float4 v, uint32_t* base, int idx) {
    *reinterpret_cast<uint2*>(base + idx) =
        make_uint2(packf16(v.x, v.y), packf16(v.z, v.w));
}
// STS B: fp16 hi + residual lo
__device__ __forceinline__ void stsB(float4 v, uint32_t* bH, uint32_t* bL, int idx) {
    uint32_t h0, l0, h1, l1;
    splitf16(v.x, v.y, h0, l0);
    splitf16(v.z, v.w, h1, l1);
    *reinterpret_cast<uint2*>(bH + idx) = make_uint2(h0, h1);
    *reinterpret_cast<uint2*>(bL + idx) = make_uint2(l0, l1);
}

// Scratch. Q/K/V single fp16 pairs. Q PRE-SCALED by 1/8 (exact, power of 2).
__device__ uint32_t g_Qf[(size_t)BHT*SEQ*HD/2];
__device__ uint32_t g_Kf[(size_t)BHT*SEQ*HD/2];
__device__ uint32_t g_Vf[(size_t)BHT*SEQ*HD/2];
__device__ float    g_OH[(size_t)MROWS*DM];      // attention out f32, [b,s,h*64+d]

// ---------------------------------------------------------------------------
// fp16 2-term mma.sync GEMM: C[8192x768] = A @ W.
// A single fp16, B = Bh + Bl residual; C = Ah.Bh + Ah.Bl.
// 128x128 CTA tile, BK=32, 8 warps (2M x 4N), double-buffered smem, 2 CTAs/SM.
// mode 0/1/2: -> g_{Q,K,V}f fp16 (Q scaled 1/8)   mode 3: A=g_OH -> lin_out
// ---------------------------------------------------------------------------
__global__ __launch_bounds__(256, 2) void mma_gemm(
    const float* __restrict__ Ain,
    const float* __restrict__ W0, const float* __restrict__ W1,
    const float* __restrict__ W2,
    float* __restrict__ lin_out, int base_mode)
{
    extern __shared__ uint32_t smg[];
    // per-buffer (u32): A 0 (128x20), Bh 2560 (32x68), Bl 4736; stride 6912
    const uint32_t BUFU = 6912;

    int mode = base_mode + blockIdx.z;
    const float* W = (mode == 0) ? W0 : (mode == 1) ? W1 : (mode == 2) ? W2 : W0;
    const float* A = (mode == 3) ? (const float*)g_OH : Ain;

    int tid  = threadIdx.x;
    int wid  = tid >> 5, lane = tid & 31;
    int warpM = wid & 1, warpN = wid >> 1;
    int m0 = blockIdx.y * 128, n0 = blockIdx.x * 128;

    float acc[4][4][4];
    #pragma unroll
    for (int i = 0; i < 4; i++)
        #pragma unroll
        for (int j = 0; j < 4; j++)
            #pragma unroll
            for (int k = 0; k < 4; k++) acc[i][j][k] = 0.f;

    uint32_t sbg = s2u(smg);
    uint32_t aLane = (uint32_t)((lane & 15) * 80 + (lane >> 4) * 16 + warpM * 5120);
    uint32_t bLane = (uint32_t)((lane & 15) * 272 + (lane >> 4) * 16 + warpN * 64);

    float4 av[4], bv[4];
    // LDG chunk 0, STS buf0
    #pragma unroll
    for (int it = 0; it < 4; it++) {
        int i = tid + it * 256;
        int r = i >> 3, c4 = (i & 7) * 4;
        av[it] = *reinterpret_cast<const float4*>(A + (size_t)(m0 + r) * DM + c4);
        int rb = i >> 5, cb = (i & 31) * 4;
        bv[it] = *reinterpret_cast<const float4*>(W + (size_t)rb * DM + n0 + cb);
    }
    #pragma unroll
    for (int it = 0; it < 4; it++) {
        int i = tid + it * 256;
        int r = i >> 3, c4 = (i & 7) * 4;
        stsA(av[it], smg, r * 20 + (c4 >> 1));
        int rb = i >> 5, cb = (i & 31) * 4;
        stsB(bv[it], smg + 2560, smg + 4736, rb * 68 + (cb >> 1));
    }
    // LDG chunk 1 into regs
    #pragma unroll
    for (int it = 0; it < 4; it++) {
        int i = tid + it * 256;
        int r = i >> 3, c4 = (i & 7) * 4;
        av[it] = *reinterpret_cast<const float4*>(A + (size_t)(m0 + r) * DM + 32 + c4);
        int rb = i >> 5, cb = (i & 31) * 4;
        bv[it] = *reinterpret_cast<const float4*>(W + (size_t)(32 + rb) * DM + n0 + cb);
    }
    __syncthreads();

    for (int c = 0; c < 24; c++) {
        if (c < 23) {
            uint32_t* base = smg + ((c + 1) & 1) * BUFU;
            #pragma unroll
            for (int it = 0; it < 4; it++) {
                int i = tid + it * 256;
                int r = i >> 3, c4 = (i & 7) * 4;
                stsA(av[it], base, r * 20 + (c4 >> 1));
                int rb = i >> 5, cb = (i & 31) * 4;
                stsB(bv[it], base + 2560, base + 4736, rb * 68 + (cb >> 1));
            }
        }
        if (c < 22) {
            int k0n = (c + 2) * 32;
            #pragma unroll
            for (int it = 0; it < 4; it++) {
                int i = tid + it * 256;
                int r = i >> 3, c4 = (i & 7) * 4;
                av[it] = *reinterpret_cast<const float4*>(
                    A + (size_t)(m0 + r) * DM + k0n + c4);
                int rb = i >> 5, cb = (i & 31) * 4;
                bv[it] = *reinterpret_cast<const float4*>(
                    W + (size_t)(k0n + rb) * DM + n0 + cb);
            }
        }
        uint32_t off = sbg + (uint32_t)(c & 1) * (BUFU * 4);
        uint32_t aH = off, bH = off + 10240, bL = off + 18944;
        #pragma unroll
        for (int ks = 0; ks < 2; ks++) {
            uint32_t bh[4][2], bl[4][2];
            #pragma unroll
            for (int np = 0; np < 2; np++) {
                uint32_t r4[4];
                ldsm_x4t(r4, bH + bLane + ks * 4352 + np * 32);
                bh[np*2][0] = r4[0]; bh[np*2][1] = r4[1];
                bh[np*2+1][0] = r4[2]; bh[np*2+1][1] = r4[3];
                ldsm_x4t(r4, bL + bLane + ks * 4352 + np * 32);
                bl[np*2][0] = r4[0]; bl[np*2][1] = r4[1];
                bl[np*2+1][0] = r4[2]; bl[np*2+1][1] = r4[3];
            }
            #pragma unroll
            for (int mtp = 0; mtp < 2; mtp++) {
                uint32_t a0h[4], a1h[4];
                ldsm_x4(a0h, aH + aLane + (2*mtp) * 1280 + ks * 32);
                ldsm_x4(a1h, aH + aLane + (2*mtp+1) * 1280 + ks * 32);
                #pragma unroll
                for (int nt = 0; nt < 4; nt++) mma_f16(acc[2*mtp][nt],   a0h, bh[nt]);
                #pragma unroll
                for (int nt = 0; nt < 4; nt++) mma_f16(acc[2*mtp+1][nt], a1h, bh[nt]);
                #pragma unroll
                for (int nt = 0; nt < 4; nt++) mma_f16(acc[2*mtp][nt],   a0h, bl[nt]);
                #pragma unroll
                for (int nt = 0; nt < 4; nt++) mma_f16(acc[2*mtp+1][nt], a1h, bl[nt]);
            }
        }
        __syncthreads();
    }

    int rl = lane >> 2, cl = (lane & 3) * 2;
    if (mode == 3) {
        #pragma unroll
        for (int mt = 0; mt < 4; mt++) {
            int m = m0 + warpM * 64 + mt * 16 + rl;
            #pragma unroll
            for (int nt = 0; nt < 4; nt++) {
                int n = n0 + warpN * 32 + nt * 8 + cl;
                *reinterpret_cast<float2*>(lin_out + (size_t)m * DM + n) =
                    make_float2(acc[mt][nt][0], acc[mt][nt][1]);
                *reinterpret_cast<float2*>(lin_out + (size_t)(m + 8) * DM + n) =
                    make_float2(acc[mt][nt][2], acc[mt][nt][3]);
            }
        }
    } else {
        // Q pre-scaled by 1/8 (exact power-of-2; bit-equivalent to post-scale)
        float alpha = (mode == 0) ? 0.125f : 1.0f;
        uint32_t* dst = (mode == 0) ? g_Qf : (mode == 1) ? g_Kf : g_Vf;
        #pragma unroll
        for (int mt = 0; mt < 4; mt++) {
            int m = m0 + warpM * 64 + mt * 16 + rl;
            int b = m >> 11, s = m & 2047;
            #pragma unroll
            for (int nt = 0; nt < 4; nt++) {
                int n = n0 + warpN * 32 + nt * 8 + cl;
                int h = n >> 6, d = n & 63;
                size_t base = ((size_t)(b * NH + h) * SEQ + s) * 32 + (d >> 1);
                dst[base] = packf16(acc[mt][nt][0] * alpha, acc[mt][nt][1] * alpha);
                dst[base + 8 * 32] = packf16(acc[mt][nt][2] * alpha, acc[mt][nt][3] * alpha);
            }
        }
    }
}

// ---------------------------------------------------------------------------
// Flash attention: fp16 single-term S (Q pre-scaled -> S is final logits),
// max-tracking online softmax, P single fp16, V single fp16.
// Double-buffered K/V/kmask, one sync + one wait per tile. ~56KB smem.
// Raw logits written with st.global.cs (streaming, never re-read).
// ---------------------------------------------------------------------------
__global__ __launch_bounds__(256, 2) void flash_mma(
    const float* __restrict__ q_mask, float* __restrict__ logits)
{
    extern __shared__ uint32_t sm32[];
    uint32_t sb = s2u(sm32);
    const uint32_t oQ = 0;
    const uint32_t oK[2]  = {18432u, 27648u};
    const uint32_t oV[2]  = {36864u, 46080u};
    const uint32_t oKM[2] = {55296u, 55552u};

    int bh = blockIdx.y;
    int b  = bh / NH;
    int h  = bh - b * NH;
    int q0 = blockIdx.x * 128;
    int tid = threadIdx.x;
    int w = tid >> 5, lane = tid & 31;
    int rq = lane >> 2, cq = lane & 3;

    #pragma unroll
    for (int it = 0; it < 4; it++) {
        int i = tid + it * 256;
        int r = i >> 3, ch = i & 7;
        size_t src = ((size_t)(bh * SEQ + q0 + r)) * 32 + ch * 4;
        cpa16(sb + oQ + r * 144 + ch * 16, g_Qf + src);
    }
    #pragma unroll
    for (int it = 0; it < 2; it++) {
        int i = tid + it * 256;
        int r = i >> 3, ch = i & 7;
        size_t src = ((size_t)(bh * SEQ + r)) * 32 + ch * 4;
        cpa16(sb + oK[0] + r * 144 + ch * 16, g_Kf + src);
        cpa16(sb + oV[0] + r * 144 + ch * 16, g_Vf + src);
    }
    if (tid < 16)
        cpa16(sb + oKM[0] + tid * 16, q_mask + (size_t)b * SEQ + tid * 4);
    CP_COMMIT();

    int rowA = 16 * w + rq;
    float qmA = q_mask[(size_t)b * SEQ + q0 + rowA];
    float qmB = q_mask[(size_t)b * SEQ + q0 + rowA + 8];
    float mA = -3.0e38f, mB = -3.0e38f, sA = 0.f, sB = 0.f;
    float o[8][4];
    #pragma unroll
    for (int i = 0; i < 8; i++)
        #pragma unroll
        for (int j = 0; j < 4; j++) o[i][j] = 0.f;
    uint32_t qh[4][4];

    float* LA = logits + ((size_t)bh * SEQ + q0 + rowA) * SEQ + 2 * cq;
    float* LB = LA + (size_t)8 * SEQ;

    for (int t = 0; t < 32; t++) {
        int k0 = t * 64;
        int bi = t & 1;
        CP_WAIT0();
        __syncthreads();

        if (t == 0) {
            uint32_t qoff = (uint32_t)((16 * w + (lane & 15)) * 144 + (lane >> 4) * 16);
            #pragma unroll
            for (int ks = 0; ks < 4; ks++)
                ldsm_x4(qh[ks], sb + oQ + qoff + ks * 32);
        }
        if (t + 1 < 32) {
            int nb = (t + 1) & 1;
            int k1 = k0 + 64;
            #pragma unroll
            for (int it = 0; it < 2; it++) {
                int i = tid + it * 256;
                int r = i >> 3, ch = i & 7;
                size_t src = ((size_t)(bh * SEQ + k1 + r)) * 32 + ch * 4;
                cpa16(sb + oK[nb] + r * 144 + ch * 16, g_Kf + src);
                cpa16(sb + oV[nb] + r * 144 + ch * 16, g_Vf + src);
            }
            if (tid < 16)
                cpa16(sb + oKM[nb] + tid * 16, q_mask + (size_t)b * SEQ + k1 + tid * 4);
            CP_COMMIT();
        }

        // ---- S = Q.K^T (Q pre-scaled: S is final raw logits) ----
        uint32_t kb = sb + oK[bi];
        float s[8][4];
        #pragma unroll
        for (int i = 0; i < 8; i++)
            #pragma unroll
            for (int j = 0; j < 4; j++) s[i][j] = 0.f;
        #pragma unroll
        for (int ks = 0; ks < 4; ks++) {
            uint32_t kf[4][4];
            #pragma unroll
            for (int g = 0; g < 4; g++) {
                uint32_t koff = (uint32_t)((16 * g + (lane & 15)) * 144
                                           + (lane >> 4) * 16 + ks * 32);
                ldsm_x4(kf[g], kb + koff);
            }
            #pragma unroll
            for (int g = 0; g < 4; g++) { uint32_t b2[2] = {kf[g][0], kf[g][2]}; mma_f16(s[2*g],   qh[ks], b2); }
            #pragma unroll
            for (int g = 0; g < 4; g++) { uint32_t b2[2] = {kf[g][1], kf[g][3]}; mma_f16(s[2*g+1], qh[ks], b2); }
        }

        // raw logits out (streaming stores)
        #pragma unroll
        for (int j = 0; j < 8; j++) {
            stg_cs_f2(LA + k0 + 8 * j, s[j][0], s[j][1]);
            stg_cs_f2(LB + k0 + 8 * j, s[j][2], s[j][3]);
        }

        const float* smKM = reinterpret_cast<const float*>(
            reinterpret_cast<const char*>(sm32) + oKM[bi]);
        float mxA = -3.0e38f, mxB = -3.0e38f;
        #pragma unroll
        for (int j = 0; j < 8; j++) {
            float km0 = smKM[8 * j + 2 * cq], km1 = smKM[8 * j + 2 * cq + 1];
            float uA0 = 1.0f - qmA * km0, uA1 = 1.0f - qmA * km1;
            float uB0 = 1.0f - qmB * km0, uB1 = 1.0f - qmB * km1;
            s[j][0] = fmaf(-1e5f, uA0, s[j][0]);
            s[j][1] = fmaf(-1e5f, uA1, s[j][1]);
            s[j][2] = fmaf(-1e5f, uB0, s[j][2]);
            s[j][3] = fmaf(-1e5f, uB1, s[j][3]);
            mxA = fmaxf(mxA, fmaxf(s[j][0], s[j][1]));
            mxB = fmaxf(mxB, fmaxf(s[j][2], s[j][3]));
        }
        mxA = fmaxf(mxA, __shfl_xor_sync(0xffffffffu, mxA, 1));
        mxA = fmaxf(mxA, __shfl_xor_sync(0xffffffffu, mxA, 2));
        mxB = fmaxf(mxB, __shfl_xor_sync(0xffffffffu, mxB, 1));
        mxB = fmaxf(mxB, __shfl_xor_sync(0xffffffffu, mxB, 2));
        float mnA = fmaxf(mA, mxA), mnB = fmaxf(mB, mxB);
        float rsA = __expf(mA - mnA), rsB = __expf(mB - mnB);
        mA = mnA; mB = mnB;
        sA *= rsA; sB *= rsB;
        #pragma unroll
        for (int j = 0; j < 8; j++) {
            s[j][0] = __expf(s[j][0] - mnA);
            s[j][1] = __expf(s[j][1] - mnA);
            s[j][2] = __expf(s[j][2] - mnB);
            s[j][3] = __expf(s[j][3] - mnB);
            sA += s[j][0] + s[j][1];
            sB += s[j][2] + s[j][3];
        }
        #pragma unroll
        for (int dt = 0; dt < 8; dt++) {
            o[dt][0] *= rsA; o[dt][1] *= rsA;
            o[dt][2] *= rsB; o[dt][3] *= rsB;
        }

        // ---- O += P.V ----
        uint32_t vb = sb + oV[bi];
        #pragma unroll
        for (int ks = 0; ks < 4; ks++) {
            uint32_t pa[4];
            pa[0] = packf16(s[2*ks][0],   s[2*ks][1]);
            pa[1] = packf16(s[2*ks][2],   s[2*ks][3]);
            pa[2] = packf16(s[2*ks+1][0], s[2*ks+1][1]);
            pa[3] = packf16(s[2*ks+1][2], s[2*ks+1][3]);
            uint32_t vf[4][4];
            #pragma unroll
            for (int dg = 0; dg < 4; dg++) {
                uint32_t voff = (uint32_t)((16 * ks + (lane & 15)) * 144
                                           + (lane >> 4) * 16 + dg * 32);
                ldsm_x4t(vf[dg], vb + voff);
            }
            #pragma unroll
            for (int dg = 0; dg < 4; dg++) { uint32_t b2[2] = {vf[dg][0], vf[dg][1]}; mma_f16(o[2*dg],   pa, b2); }
            #pragma unroll
            for (int dg = 0; dg < 4; dg++) { uint32_t b2[2] = {vf[dg][2], vf[dg][3]}; mma_f16(o[2*dg+1], pa, b2); }
        }
    }

    sA += __shfl_xor_sync(0xffffffffu, sA, 1);
    sA += __shfl_xor_sync(0xffffffffu, sA, 2);
    sB += __shfl_xor_sync(0xffffffffu, sB, 1);
    sB += __shfl_xor_sync(0xffffffffu, sB, 2);
    float invA = 1.0f / sA, invB = 1.0f / sB;
    float* OA = g_OH + ((size_t)b * SEQ + q0 + rowA) * DM + h * HD + 2 * cq;
    float* OB = OA + (size_t)8 * DM;
    #pragma unroll
    for (int dt = 0; dt < 8; dt++) {
        *reinterpret_cast<float2*>(OA + 8 * dt) =
            make_float2(o[dt][0] * invA, o[dt][1] * invA);
        *reinterpret_cast<float2*>(OB + 8 * dt) =
            make_float2(o[dt][2] * invB, o[dt][3] * invB);
    }
}

// ---------------------------------------------------------------------------
// Launch. Output: [out (4*2048*768)] then [logits_raw (48*2048*2048)]
// ---------------------------------------------------------------------------
extern "C" void kernel_launch(void* const* d_in, const int* in_sizes, int n_in,
                              void* d_out, int out_size)
{
    const float* x  = (const float*)d_in[0];
    const float* qm = (const float*)d_in[1];
    const float* Wq = (const float*)d_in[2];
    const float* Wk = (const float*)d_in[3];
    const float* Wv = (const float*)d_in[4];
    const float* Wo = (const float*)d_in[5];

    float* out    = (float*)d_out;
    float* logits = out + (size_t)MROWS * DM;

    const int GEMM_SMEM  = 55296;   // 2 x 6912 u32
    const int FLASH_SMEM = 55808;
    cudaFuncSetAttribute(mma_gemm,
                         cudaFuncAttributeMaxDynamicSharedMemorySize, GEMM_SMEM);
    cudaFuncSetAttribute(flash_mma,
                         cudaFuncAttributeMaxDynamicSharedMemorySize, FLASH_SMEM);

    mma_gemm <<<dim3(6, 64, 3), 256, GEMM_SMEM>>>(x, Wq, Wk, Wv, nullptr, 0);
    flash_mma<<<dim3(16, 48), 256, FLASH_SMEM>>>(qm, logits);
    mma_gemm <<<dim3(6, 64, 1), 256, GEMM_SMEM>>>(nullptr, Wo, Wo, Wo, out, 3);
}

// round 15
// speedup vs baseline: 1.4076x; 1.0782x over previous
#include <cuda_runtime.h>
#include <cuda_fp16.h>
#include <math.h>
#include <stdint.h>

#define BATCH 4
#define SEQ   2048
#define DM    768
#define NH    12
#define HD    64
#define MROWS (BATCH*SEQ)   // 8192
#define BHT   (BATCH*NH)    // 48

// ---------------- misc helpers ----------------
__device__ __forceinline__ uint32_t s2u(const void* p) {
    uint32_t a;
    asm("{ .reg .u64 t; cvta.to.shared.u64 t, %1; cvt.u32.u64 %0, t; }"
        : "=r"(a) : "l"(p));
    return a;
}
// cp.async 16B (sm_80 PTX)
__device__ __forceinline__ void cpa16(uint32_t dst, const void* src) {
    asm volatile("cp.async.cg.shared.global [%0], [%1], 16;"
                 :: "r"(dst), "l"(src) : "memory");
}
#define CP_COMMIT() asm volatile("cp.async.commit_group;" ::: "memory")
#define CP_WAIT0()  asm volatile("cp.async.wait_group 0;" ::: "memory")
// streaming store (evict-first): logits written once, never read
__device__ __forceinline__ void stg_cs_f2(float* p, float a, float b) {
    asm volatile("st.global.cs.v2.f32 [%0], {%1,%2};"
                 :: "l"(p), "f"(a), "f"(b) : "memory");
}

// ---------------- mma.sync helpers (sm_80 PTX, legacy HMMA) ----------------
__device__ __forceinline__ void ldsm_x4(uint32_t* r, uint32_t addr) {
    asm volatile("ldmatrix.sync.aligned.m8n8.x4.shared.b16 {%0,%1,%2,%3}, [%4];"
                 : "=r"(r[0]), "=r"(r[1]), "=r"(r[2]), "=r"(r[3]) : "r"(addr));
}
__device__ __forceinline__ void ldsm_x4t(uint32_t* r, uint32_t addr) {
    asm volatile("ldmatrix.sync.aligned.m8n8.x4.trans.shared.b16 {%0,%1,%2,%3}, [%4];"
                 : "=r"(r[0]), "=r"(r[1]), "=r"(r[2]), "=r"(r[3]) : "r"(addr));
}
// fp16 mma
__device__ __forceinline__ void mma_f16(float* c, const uint32_t* a, const uint32_t* b) {
    asm volatile(
        "mma.sync.aligned.m16n8k16.row.col.f32.f16.f16.f32 "
        "{%0,%1,%2,%3}, {%4,%5,%6,%7}, {%8,%9}, {%0,%1,%2,%3};"
        : "+f"(c[0]), "+f"(c[1]), "+f"(c[2]), "+f"(c[3])
        : "r"(a[0]), "r"(a[1]), "r"(a[2]), "r"(a[3]), "r"(b[0]), "r"(b[1]));
}
// fp16 pack (low half = a)
__device__ __forceinline__ uint32_t packf16(float a, float b) {
    __half2 h = __floats2half2_rn(a, b);
    return *reinterpret_cast<uint32_t*>(&h);
}
// fp16 split: hi pair + residual pair
__device__ __forceinline__ void splitf16(float a, float b, uint32_t& h, uint32_t& l) {
    __half2 hh = __floats2half2_rn(a, b);
    float2 bk = __half22float2(hh);
    __half2 ll = __floats2half2_rn(a - bk.x, b - bk.y);
    h = *reinterpret_cast<uint32_t*>(&hh);
    l = *reinterpret_cast<uint32_t*>(&ll);
}
// STS B: fp16 hi + residual lo
__device__ __forceinline__ void stsB(float4 v, uint32_t* bH, uint32_t* bL, int idx) {
    uint32_t h0, l0, h1, l1;
    splitf16(v.x, v.y, h0, l0);
    splitf16(v.z, v.w, h1, l1);
    *reinterpret_cast<uint2*>(bH + idx) = make_uint2(h0, h1);
    *reinterpret_cast<uint2*>(bL + idx) = make_uint2(l0, l1);
}

// Scratch. Q/K/V single fp16 pairs. Q PRE-SCALED by 1/8 (exact, power of 2).
__device__ uint32_t g_Qf[(size_t)BHT*SEQ*HD/2];
__device__ uint32_t g_Kf[(size_t)BHT*SEQ*HD/2];
__device__ uint32_t g_Vf[(size_t)BHT*SEQ*HD/2];
__device__ uint32_t g_Xf[(size_t)MROWS*DM/2];    // x as fp16 pairs (row stride 384 u32)
__device__ uint32_t g_OHf[(size_t)MROWS*DM/2];   // attention out fp16 pairs

// ---------------------------------------------------------------------------
// Prologue: x f32 -> fp16 pairs (one float4 -> uint2 per thread).
// ---------------------------------------------------------------------------
__global__ __launch_bounds__(256) void cvt_x_kernel(const float* __restrict__ x)
{
    int i = blockIdx.x * 256 + threadIdx.x;   // [0, MROWS*DM/4)
    float4 v = reinterpret_cast<const float4*>(x)[i];
    reinterpret_cast<uint2*>(g_Xf)[i] =
        make_uint2(packf16(v.x, v.y), packf16(v.z, v.w));
}

// ---------------------------------------------------------------------------
// fp16 2-term mma.sync GEMM: C[8192x768] = A @ W.
// A single fp16 (pre-converted: g_Xf / g_OHf), B = Bh + Bl residual.
// 128x128 CTA tile, BK=32, 8 warps (2M x 4N), double-buffered smem, 2 CTAs/SM.
// mode 0/1/2: -> g_{Q,K,V}f fp16 (Q scaled 1/8)   mode 3: A=g_OHf -> lin_out
// ---------------------------------------------------------------------------
__global__ __launch_bounds__(256, 2) void mma_gemm(
    const float* __restrict__ W0, const float* __restrict__ W1,
    const float* __restrict__ W2,
    float* __restrict__ lin_out, int base_mode)
{
    extern __shared__ uint32_t smg[];
    // per-buffer (u32): A 0 (128x20), Bh 2560 (32x68), Bl 4736; stride 6912
    const uint32_t BUFU = 6912;

    int mode = base_mode + blockIdx.z;
    const float* W = (mode == 0) ? W0 : (mode == 1) ? W1 : (mode == 2) ? W2 : W0;
    const uint32_t* A16 = (mode == 3) ? g_OHf : g_Xf;   // fp16 pairs, stride 384

    int tid  = threadIdx.x;
    int wid  = tid >> 5, lane = tid & 31;
    int warpM = wid & 1, warpN = wid >> 1;
    int m0 = blockIdx.y * 128, n0 = blockIdx.x * 128;

    float acc[4][4][4];
    #pragma unroll
    for (int i = 0; i < 4; i++)
        #pragma unroll
        for (int j = 0; j < 4; j++)
            #pragma unroll
            for (int k = 0; k < 4; k++) acc[i][j][k] = 0.f;

    uint32_t sbg = s2u(smg);
    uint32_t aLane = (uint32_t)((lane & 15) * 80 + (lane >> 4) * 16 + warpM * 5120);
    uint32_t bLane = (uint32_t)((lane & 15) * 272 + (lane >> 4) * 16 + warpN * 64);

    uint4 av[2];
    float4 bv[4];
    // LDG chunk 0, STS buf0
    #pragma unroll
    for (int it = 0; it < 2; it++) {
        int i = tid + it * 256;           // 0..511
        int r = i >> 2, j = i & 3;        // 128 rows x 4 uint4
        av[it] = *reinterpret_cast<const uint4*>(A16 + (size_t)(m0 + r) * 384 + j * 4);
    }
    #pragma unroll
    for (int it = 0; it < 4; it++) {
        int i = tid + it * 256;
        int rb = i >> 5, cb = (i & 31) * 4;
        bv[it] = *reinterpret_cast<const float4*>(W + (size_t)rb * DM + n0 + cb);
    }
    #pragma unroll
    for (int it = 0; it < 2; it++) {
        int i = tid + it * 256;
        int r = i >> 2, j = i & 3;
        int idx = r * 20 + j * 4;
        *reinterpret_cast<uint2*>(smg + idx)     = make_uint2(av[it].x, av[it].y);
        *reinterpret_cast<uint2*>(smg + idx + 2) = make_uint2(av[it].z, av[it].w);
    }
    #pragma unroll
    for (int it = 0; it < 4; it++) {
        int i = tid + it * 256;
        int rb = i >> 5, cb = (i & 31) * 4;
        stsB(bv[it], smg + 2560, smg + 4736, rb * 68 + (cb >> 1));
    }
    // LDG chunk 1 into regs
    #pragma unroll
    for (int it = 0; it < 2; it++) {
        int i = tid + it * 256;
        int r = i >> 2, j = i & 3;
        av[it] = *reinterpret_cast<const uint4*>(A16 + (size_t)(m0 + r) * 384 + 16 + j * 4);
    }
    #pragma unroll
    for (int it = 0; it < 4; it++) {
        int i = tid + it * 256;
        int rb = i >> 5, cb = (i & 31) * 4;
        bv[it] = *reinterpret_cast<const float4*>(W + (size_t)(32 + rb) * DM + n0 + cb);
    }
    __syncthreads();

    for (int c = 0; c < 24; c++) {
        if (c < 23) {
            uint32_t* base = smg + ((c + 1) & 1) * BUFU;
            #pragma unroll
            for (int it = 0; it < 2; it++) {
                int i = tid + it * 256;
                int r = i >> 2, j = i & 3;
                int idx = r * 20 + j * 4;
                *reinterpret_cast<uint2*>(base + idx)     = make_uint2(av[it].x, av[it].y);
                *reinterpret_cast<uint2*>(base + idx + 2) = make_uint2(av[it].z, av[it].w);
            }
            #pragma unroll
            for (int it = 0; it < 4; it++) {
                int i = tid + it * 256;
                int rb = i >> 5, cb = (i & 31) * 4;
                stsB(bv[it], base + 2560, base + 4736, rb * 68 + (cb >> 1));
            }
        }
        if (c < 22) {
            int k0n = (c + 2) * 32;
            #pragma unroll
            for (int it = 0; it < 2; it++) {
                int i = tid + it * 256;
                int r = i >> 2, j = i & 3;
                av[it] = *reinterpret_cast<const uint4*>(
                    A16 + (size_t)(m0 + r) * 384 + (k0n >> 1) + j * 4);
            }
            #pragma unroll
            for (int it = 0; it < 4; it++) {
                int i = tid + it * 256;
                int rb = i >> 5, cb = (i & 31) * 4;
                bv[it] = *reinterpret_cast<const float4*>(
                    W + (size_t)(k0n + rb) * DM + n0 + cb);
            }
        }
        uint32_t off = sbg + (uint32_t)(c & 1) * (BUFU * 4);
        uint32_t aH = off, bH = off + 10240, bL = off + 18944;
        #pragma unroll
        for (int ks = 0; ks < 2; ks++) {
            uint32_t bh[4][2], bl[4][2];
            #pragma unroll
            for (int np = 0; np < 2; np++) {
                uint32_t r4[4];
                ldsm_x4t(r4, bH + bLane + ks * 4352 + np * 32);
                bh[np*2][0] = r4[0]; bh[np*2][1] = r4[1];
                bh[np*2+1][0] = r4[2]; bh[np*2+1][1] = r4[3];
                ldsm_x4t(r4, bL + bLane + ks * 4352 + np * 32);
                bl[np*2][0] = r4[0]; bl[np*2][1] = r4[1];
                bl[np*2+1][0] = r4[2]; bl[np*2+1][1] = r4[3];
            }
            #pragma unroll
            for (int mtp = 0; mtp < 2; mtp++) {
                uint32_t a0h[4], a1h[4];
                ldsm_x4(a0h, aH + aLane + (2*mtp) * 1280 + ks * 32);
                ldsm_x4(a1h, aH + aLane + (2*mtp+1) * 1280 + ks * 32);
                #pragma unroll
                for (int nt = 0; nt < 4; nt++) mma_f16(acc[2*mtp][nt],   a0h, bh[nt]);
                #pragma unroll
                for (int nt = 0; nt < 4; nt++) mma_f16(acc[2*mtp+1][nt], a1h, bh[nt]);
                #pragma unroll
                for (int nt = 0; nt < 4; nt++) mma_f16(acc[2*mtp][nt],   a0h, bl[nt]);
                #pragma unroll
                for (int nt = 0; nt < 4; nt++) mma_f16(acc[2*mtp+1][nt], a1h, bl[nt]);
            }
        }
        __syncthreads();
    }

    int rl = lane >> 2, cl = (lane & 3) * 2;
    if (mode == 3) {
        #pragma unroll
        for (int mt = 0; mt < 4; mt++) {
            int m = m0 + warpM * 64 + mt * 16 + rl;
            #pragma unroll
            for (int nt = 0; nt < 4; nt++) {
                int n = n0 + warpN * 32 + nt * 8 + cl;
                *reinterpret_cast<float2*>(lin_out + (size_t)m * DM + n) =
                    make_float2(acc[mt][nt][0], acc[mt][nt][1]);
                *reinterpret_cast<float2*>(lin_out + (size_t)(m + 8) * DM + n) =
                    make_float2(acc[mt][nt][2], acc[mt][nt][3]);
            }
        }
    } else {
        // Q pre-scaled by 1/8 (exact power-of-2; bit-equivalent to post-scale)
        float alpha = (mode == 0) ? 0.125f : 1.0f;
        uint32_t* dst = (mode == 0) ? g_Qf : (mode == 1) ? g_Kf : g_Vf;
        #pragma unroll
        for (int mt = 0; mt < 4; mt++) {
            int m = m0 + warpM * 64 + mt * 16 + rl;
            int b = m >> 11, s = m & 2047;
            #pragma unroll
            for (int nt = 0; nt < 4; nt++) {
                int n = n0 + warpN * 32 + nt * 8 + cl;
                int h = n >> 6, d = n & 63;
                size_t base = ((size_t)(b * NH + h) * SEQ + s) * 32 + (d >> 1);
                dst[base] = packf16(acc[mt][nt][0] * alpha, acc[mt][nt][1] * alpha);
                dst[base + 8 * 32] = packf16(acc[mt][nt][2] * alpha, acc[mt][nt][3] * alpha);
            }
        }
    }
}

// ---------------------------------------------------------------------------
// Flash attention: fp16 single-term S (Q pre-scaled -> S is final logits),
// max-tracking online softmax, P single fp16, V single fp16.
// Double-buffered K/V/kmask, one sync + one wait per tile. ~56KB smem.
// O written as fp16 pairs to g_OHf.
// ---------------------------------------------------------------------------
__global__ __launch_bounds__(256, 2) void flash_mma(
    const float* __restrict__ q_mask, float* __restrict__ logits)
{
    extern __shared__ uint32_t sm32[];
    uint32_t sb = s2u(sm32);
    const uint32_t oQ = 0;
    const uint32_t oK[2]  = {18432u, 27648u};
    const uint32_t oV[2]  = {36864u, 46080u};
    const uint32_t oKM[2] = {55296u, 55552u};

    int bh = blockIdx.y;
    int b  = bh / NH;
    int h  = bh - b * NH;
    int q0 = blockIdx.x * 128;
    int tid = threadIdx.x;
    int w = tid >> 5, lane = tid & 31;
    int rq = lane >> 2, cq = lane & 3;

    #pragma unroll
    for (int it = 0; it < 4; it++) {
        int i = tid + it * 256;
        int r = i >> 3, ch = i & 7;
        size_t src = ((size_t)(bh * SEQ + q0 + r)) * 32 + ch * 4;
        cpa16(sb + oQ + r * 144 + ch * 16, g_Qf + src);
    }
    #pragma unroll
    for (int it = 0; it < 2; it++) {
        int i = tid + it * 256;
        int r = i >> 3, ch = i & 7;
        size_t src = ((size_t)(bh * SEQ + r)) * 32 + ch * 4;
        cpa16(sb + oK[0] + r * 144 + ch * 16, g_Kf + src);
        cpa16(sb + oV[0] + r * 144 + ch * 16, g_Vf + src);
    }
    if (tid < 16)
        cpa16(sb + oKM[0] + tid * 16, q_mask + (size_t)b * SEQ + tid * 4);
    CP_COMMIT();

    int rowA = 16 * w + rq;
    float qmA = q_mask[(size_t)b * SEQ + q0 + rowA];
    float qmB = q_mask[(size_t)b * SEQ + q0 + rowA + 8];
    float mA = -3.0e38f, mB = -3.0e38f, sA = 0.f, sB = 0.f;
    float o[8][4];
    #pragma unroll
    for (int i = 0; i < 8; i++)
        #pragma unroll
        for (int j = 0; j < 4; j++) o[i][j] = 0.f;
    uint32_t qh[4][4];

    float* LA = logits + ((size_t)bh * SEQ + q0 + rowA) * SEQ + 2 * cq;
    float* LB = LA + (size_t)8 * SEQ;

    for (int t = 0; t < 32; t++) {
        int k0 = t * 64;
        int bi = t & 1;
        CP_WAIT0();
        __syncthreads();

        if (t == 0) {
            uint32_t qoff = (uint32_t)((16 * w + (lane & 15)) * 144 + (lane >> 4) * 16);
            #pragma unroll
            for (int ks = 0; ks < 4; ks++)
                ldsm_x4(qh[ks], sb + oQ + qoff + ks * 32);
        }
        if (t + 1 < 32) {
            int nb = (t + 1) & 1;
            int k1 = k0 + 64;
            #pragma unroll
            for (int it = 0; it < 2; it++) {
                int i = tid + it * 256;
                int r = i >> 3, ch = i & 7;
                size_t src = ((size_t)(bh * SEQ + k1 + r)) * 32 + ch * 4;
                cpa16(sb + oK[nb] + r * 144 + ch * 16, g_Kf + src);
                cpa16(sb + oV[nb] + r * 144 + ch * 16, g_Vf + src);
            }
            if (tid < 16)
                cpa16(sb + oKM[nb] + tid * 16, q_mask + (size_t)b * SEQ + k1 + tid * 4);
            CP_COMMIT();
        }

        // ---- S = Q.K^T (Q pre-scaled: S is final raw logits) ----
        uint32_t kb = sb + oK[bi];
        float s[8][4];
        #pragma unroll
        for (int i = 0; i < 8; i++)
            #pragma unroll
            for (int j = 0; j < 4; j++) s[i][j] = 0.f;
        #pragma unroll
        for (int ks = 0; ks < 4; ks++) {
            uint32_t kf[4][4];
            #pragma unroll
            for (int g = 0; g < 4; g++) {
                uint32_t koff = (uint32_t)((16 * g + (lane & 15)) * 144
                                           + (lane >> 4) * 16 + ks * 32);
                ldsm_x4(kf[g], kb + koff);
            }
            #pragma unroll
            for (int g = 0; g < 4; g++) { uint32_t b2[2] = {kf[g][0], kf[g][2]}; mma_f16(s[2*g],   qh[ks], b2); }
            #pragma unroll
            for (int g = 0; g < 4; g++) { uint32_t b2[2] = {kf[g][1], kf[g][3]}; mma_f16(s[2*g+1], qh[ks], b2); }
        }

        // raw logits out (streaming stores)
        #pragma unroll
        for (int j = 0; j < 8; j++) {
            stg_cs_f2(LA + k0 + 8 * j, s[j][0], s[j][1]);
            stg_cs_f2(LB + k0 + 8 * j, s[j][2], s[j][3]);
        }

        const float* smKM = reinterpret_cast<const float*>(
            reinterpret_cast<const char*>(sm32) + oKM[bi]);
        float mxA = -3.0e38f, mxB = -3.0e38f;
        #pragma unroll
        for (int j = 0; j < 8; j++) {
            float km0 = smKM[8 * j + 2 * cq], km1 = smKM[8 * j + 2 * cq + 1];
            float uA0 = 1.0f - qmA * km0, uA1 = 1.0f - qmA * km1;
            float uB0 = 1.0f - qmB * km0, uB1 = 1.0f - qmB * km1;
            s[j][0] = fmaf(-1e5f, uA0, s[j][0]);
            s[j][1] = fmaf(-1e5f, uA1, s[j][1]);
            s[j][2] = fmaf(-1e5f, uB0, s[j][2]);
            s[j][3] = fmaf(-1e5f, uB1, s[j][3]);
            mxA = fmaxf(mxA, fmaxf(s[j][0], s[j][1]));
            mxB = fmaxf(mxB, fmaxf(s[j][2], s[j][3]));
        }
        mxA = fmaxf(mxA, __shfl_xor_sync(0xffffffffu, mxA, 1));
        mxA = fmaxf(mxA, __shfl_xor_sync(0xffffffffu, mxA, 2));
        mxB = fmaxf(mxB, __shfl_xor_sync(0xffffffffu, mxB, 1));
        mxB = fmaxf(mxB, __shfl_xor_sync(0xffffffffu, mxB, 2));
        float mnA = fmaxf(mA, mxA), mnB = fmaxf(mB, mxB);
        float rsA = __expf(mA - mnA), rsB = __expf(mB - mnB);
        mA = mnA; mB = mnB;
        sA *= rsA; sB *= rsB;
        #pragma unroll
        for (int j = 0; j < 8; j++) {
            s[j][0] = __expf(s[j][0] - mnA);
            s[j][1] = __expf(s[j][1] - mnA);
            s[j][2] = __expf(s[j][2] - mnB);
            s[j][3] = __expf(s[j][3] - mnB);
            sA += s[j][0] + s[j][1];
            sB += s[j][2] + s[j][3];
        }
        #pragma unroll
        for (int dt = 0; dt < 8; dt++) {
            o[dt][0] *= rsA; o[dt][1] *= rsA;
            o[dt][2] *= rsB; o[dt][3] *= rsB;
        }

        // ---- O += P.V ----
        uint32_t vb = sb + oV[bi];
        #pragma unroll
        for (int ks = 0; ks < 4; ks++) {
            uint32_t pa[4];
            pa[0] = packf16(s[2*ks][0],   s[2*ks][1]);
            pa[1] = packf16(s[2*ks][2],   s[2*ks][3]);
            pa[2] = packf16(s[2*ks+1][0], s[2*ks+1][1]);
            pa[3] = packf16(s[2*ks+1][2], s[2*ks+1][3]);
            uint32_t vf[4][4];
            #pragma unroll
            for (int dg = 0; dg < 4; dg++) {
                uint32_t voff = (uint32_t)((16 * ks + (lane & 15)) * 144
                                           + (lane >> 4) * 16 + dg * 32);
                ldsm_x4t(vf[dg], vb + voff);
            }
            #pragma unroll
            for (int dg = 0; dg < 4; dg++) { uint32_t b2[2] = {vf[dg][0], vf[dg][1]}; mma_f16(o[2*dg],   pa, b2); }
            #pragma unroll
            for (int dg = 0; dg < 4; dg++) { uint32_t b2[2] = {vf[dg][2], vf[dg][3]}; mma_f16(o[2*dg+1], pa, b2); }
        }
    }

    sA += __shfl_xor_sync(0xffffffffu, sA, 1);
    sA += __shfl_xor_sync(0xffffffffu, sA, 2);
    sB += __shfl_xor_sync(0xffffffffu, sB, 1);
    sB += __shfl_xor_sync(0xffffffffu, sB, 2);
    float invA = 1.0f / sA, invB = 1.0f / sB;
    // O -> g_OHf fp16 pairs. u32 row stride 384; col offset (h*64 + 2*cq)/2.
    uint32_t* OA = g_OHf + ((size_t)b * SEQ + q0 + rowA) * 384 + h * 32 + cq;
    uint32_t* OB = OA + (size_t)8 * 384;
    #pragma unroll
    for (int dt = 0; dt < 8; dt++) {
        OA[4 * dt] = packf16(o[dt][0] * invA, o[dt][1] * invA);
        OB[4 * dt] = packf16(o[dt][2] * invB, o[dt][3] * invB);
    }
}

// ---------------------------------------------------------------------------
// Launch. Output: [out (4*2048*768)] then [logits_raw (48*2048*2048)]
// ---------------------------------------------------------------------------
extern "C" void kernel_launch(void* const* d_in, const int* in_sizes, int n_in,
                              void* d_out, int out_size)
{
    const float* x  = (const float*)d_in[0];
    const float* qm = (const float*)d_in[1];
    const float* Wq = (const float*)d_in[2];
    const float* Wk = (const float*)d_in[3];
    const float* Wv = (const float*)d_in[4];
    const float* Wo = (const float*)d_in[5];

    float* out    = (float*)d_out;
    float* logits = out + (size_t)MROWS * DM;

    const int GEMM_SMEM  = 55296;   // 2 x 6912 u32
    const int FLASH_SMEM = 55808;
    cudaFuncSetAttribute(mma_gemm,
                         cudaFuncAttributeMaxDynamicSharedMemorySize, GEMM_SMEM);
    cudaFuncSetAttribute(flash_mma,
                         cudaFuncAttributeMaxDynamicSharedMemorySize, FLASH_SMEM);

    cvt_x_kernel<<<MROWS * DM / 4 / 256, 256>>>(x);
    mma_gemm <<<dim3(6, 64, 3), 256, GEMM_SMEM>>>(Wq, Wk, Wv, nullptr, 0);
    flash_mma<<<dim3(16, 48), 256, FLASH_SMEM>>>(qm, logits);
    mma_gemm <<<dim3(6, 64, 1), 256, GEMM_SMEM>>>(Wo, Wo, Wo, out, 3);
}